// round 12
// baseline (speedup 1.0000x reference)
#include <cuda_runtime.h>
#include <cuda_fp16.h>
#include <cstdint>

#define Bn 2
#define Tn 2048
#define Cn 1024
#define Hn 16
#define HDn 64
#define BTn (Bn*Tn)

// Scratch (no allocations allowed) — all fp16 in packed fragment layouts.
__device__ __half g_qp[Bn*Hn*Tn*HDn];     // Q A-frag (per head), *0.125
__device__ __half g_kp[Bn*Hn*Tn*HDn];     // K B-frag (S)
__device__ __half g_vp[Bn*Hn*Tn*HDn];     // V B-frag (PV)
__device__ __half g_xp[(size_t)BTn*Cn];   // x, A-frag
__device__ __half g_yp[(size_t)BTn*Cn];   // attn out, A-frag
__device__ __half g_wt[3*Cn*Cn];          // w_attn, B-frag
__device__ __half g_wp[Cn*Cn];            // w_proj, B-frag

__device__ __forceinline__ uint32_t h2pk(float a, float b) {
    __half2 h = __floats2half2_rn(a, b);
    return *(uint32_t*)&h;
}

__device__ __forceinline__ uint32_t smem_u32(const void* p) {
    uint32_t a;
    asm("{ .reg .u64 t; cvta.to.shared.u64 t, %1; cvt.u32.u64 %0, t; }"
        : "=r"(a) : "l"(p));
    return a;
}

__device__ __forceinline__ void cp16(uint32_t sdst, const void* gsrc) {
    asm volatile("cp.async.cg.shared.global [%0], [%1], 16;"
                 :: "r"(sdst), "l"(gsrc) : "memory");
}
#define CP_COMMIT() asm volatile("cp.async.commit_group;" ::: "memory")
#define CP_WAIT(n)  asm volatile("cp.async.wait_group %0;" :: "n"(n) : "memory")

// D = A@B + D, m16n8k16 fp16 inputs, fp32 accum. A row-major, B col-major.
__device__ __forceinline__ void mma_f16(float* d, const uint32_t* a, uint32_t b0, uint32_t b1) {
    asm volatile("mma.sync.aligned.m16n8k16.row.col.f32.f16.f16.f32 "
        "{%0,%1,%2,%3}, {%4,%5,%6,%7}, {%8,%9}, {%0,%1,%2,%3};\n"
        : "+f"(d[0]), "+f"(d[1]), "+f"(d[2]), "+f"(d[3])
        : "r"(a[0]), "r"(a[1]), "r"(a[2]), "r"(a[3]), "r"(b0), "r"(b1));
}

// ---------------------------------------------------------------------------
// Prep: pack A[M,K] fp32 -> fp16 A-frag order (m16n8k16).
// ---------------------------------------------------------------------------
__global__ __launch_bounds__(256)
void pack_a(const float* __restrict__ src, __half* __restrict__ dst, int K)
{
    __shared__ float s[16][260];
    const int m16 = blockIdx.x;
    const int k0  = blockIdx.y * 256;
    const int K16 = K >> 4;
    const int tid = threadIdx.x;

    #pragma unroll
    for (int i = 0; i < 4; i++) {
        int j = tid + 256 * i;
        int r = j >> 6, c4 = (j & 63) * 4;
        *(float4*)&s[r][c4] = *(const float4*)(src + (size_t)(m16 * 16 + r) * K + k0 + c4);
    }
    __syncthreads();
    uint4* d4 = (uint4*)dst;
    #pragma unroll
    for (int i = 0; i < 2; i++) {
        int item = tid + 256 * i;
        int k16f = item >> 5, lane = item & 31;
        int g = lane >> 2, t = lane & 3;
        int c = k16f * 16 + 2 * t;
        uint4 v;
        v.x = h2pk(s[g    ][c],     s[g    ][c + 1]);
        v.y = h2pk(s[g + 8][c],     s[g + 8][c + 1]);
        v.z = h2pk(s[g    ][c + 8], s[g    ][c + 9]);
        v.w = h2pk(s[g + 8][c + 8], s[g + 8][c + 9]);
        d4[(size_t)(m16 * K16 + (k0 >> 4) + k16f) * 32 + lane] = v;
    }
}

// ---------------------------------------------------------------------------
// Prep: pack W[K,N] fp32 -> fp16 B-frag order (m16n8k16).
// ---------------------------------------------------------------------------
__global__ __launch_bounds__(256)
void pack_b(const float* __restrict__ W, __half* __restrict__ dst, int K, int N)
{
    __shared__ float s[64][68];
    const int n0 = blockIdx.x * 64;
    const int k0 = blockIdx.y * 64;
    const int K16 = K >> 4;
    const int tid = threadIdx.x;

    #pragma unroll
    for (int i = 0; i < 4; i++) {
        int j = tid + 256 * i;
        int r = j >> 4, c4 = (j & 15) * 4;
        *(float4*)&s[r][c4] = *(const float4*)(W + (size_t)(k0 + r) * N + n0 + c4);
    }
    __syncthreads();
    uint2* d2 = (uint2*)dst;
    #pragma unroll
    for (int i = 0; i < 4; i++) {
        int item = tid + 256 * i;
        int f = item >> 5, lane = item & 31;
        int n8f = f >> 2, k16f = f & 3;
        int g = lane >> 2, t = lane & 3;
        int r = k16f * 16 + 2 * t, c = n8f * 8 + g;
        uint2 v;
        v.x = h2pk(s[r    ][c], s[r + 1][c]);
        v.y = h2pk(s[r + 8][c], s[r + 9][c]);
        d2[(size_t)(((n0 >> 3) + n8f) * K16 + (k0 >> 4) + k16f) * 32 + lane] = v;
    }
}

// ---------------------------------------------------------------------------
// fp16 mma.sync GEMM on fragment-packed inputs (round-11, unchanged).
// ---------------------------------------------------------------------------
#define EPITCH 132
#define GSMEM0_SZ (128 * EPITCH * 4)
#define GSMEM1_SZ (4 * 16384)

template<int OP>
__global__ __launch_bounds__(128, 2)
void gemm_pk(const __half* __restrict__ WTp,
             const float* __restrict__ bias,
             float* __restrict__ out,
             int M, int N, int K)
{
    extern __shared__ __align__(16) char smem[];
    const __half* AP = (OP == 0) ? g_xp : g_yp;
    const int K16 = K >> 4;

    const int tid  = threadIdx.x;
    const int wid  = tid >> 5;
    const int lane = tid & 31;
    const int g = lane >> 2;
    const int t = lane & 3;
    const int wm = wid >> 1;
    const int wn = wid & 1;
    const int bm = blockIdx.y * 128;
    const int bn = blockIdx.x * 128;
    const int bm16 = bm >> 4;
    const int bn8  = bn >> 3;

    const uint32_t sb = smem_u32(smem);
    const char* pa = (const char*)AP + ((size_t)bm16 * K16) * 512 + (size_t)tid * 16;
    const char* pb = (const char*)WTp + ((size_t)(bn8 + (tid >> 6)) * K16) * 256
                     + (size_t)(tid & 63) * 16;
    const uint32_t adst = sb + tid * 16;
    const uint32_t bdst = sb + 32768 + (tid >> 6) * 1024 + (tid & 63) * 16;

    float acc[4][8][4];
    #pragma unroll
    for (int mi = 0; mi < 4; mi++)
        #pragma unroll
        for (int ni = 0; ni < 8; ni++)
            #pragma unroll
            for (int e = 0; e < 4; e++) acc[mi][ni][e] = 0.f;

    const int NIT = K / 64;

    #pragma unroll
    for (int i = 0; i < 8; i++) {
        cp16(adst + i * 2048, pa + (size_t)i * K16 * 512);
        cp16(bdst + i * 2048, pb + (size_t)(2 * i) * K16 * 256);
    }
    CP_COMMIT();

    for (int it = 0; it < NIT; it++) {
        const int cur = it & 1;
        if (it + 1 < NIT) {
            const int nxt = cur ^ 1;
            const size_t ao = (size_t)(it + 1) * 2048;
            const size_t bo = (size_t)(it + 1) * 1024;
            #pragma unroll
            for (int i = 0; i < 8; i++) {
                cp16(adst + nxt * 16384 + i * 2048, pa + (size_t)i * K16 * 512 + ao);
                cp16(bdst + nxt * 16384 + i * 2048, pb + (size_t)(2 * i) * K16 * 256 + bo);
            }
            CP_COMMIT();
            CP_WAIT(1);
        } else {
            CP_WAIT(0);
        }
        __syncthreads();

        const char* As = smem + cur * 16384;
        const char* Bs = smem + 32768 + cur * 16384;
        #pragma unroll
        for (int kk = 0; kk < 4; kk++) {
            uint4 afv[4];
            uint2 bfv[8];
            #pragma unroll
            for (int mi = 0; mi < 4; mi++)
                afv[mi] = *(const uint4*)(As + ((((wm * 4 + mi) * 4 + kk) * 32 + lane) << 4));
            #pragma unroll
            for (int ni = 0; ni < 8; ni++)
                bfv[ni] = *(const uint2*)(Bs + ((((wn * 8 + ni) * 4 + kk) * 32 + lane) << 3));
            #pragma unroll
            for (int mi = 0; mi < 4; mi++) {
                uint32_t af[4] = { afv[mi].x, afv[mi].y, afv[mi].z, afv[mi].w };
                #pragma unroll
                for (int ni = 0; ni < 8; ni++)
                    mma_f16(acc[mi][ni], af, bfv[ni].x, bfv[ni].y);
            }
        }
        __syncthreads();
    }

    if (OP == 1) {
        #pragma unroll
        for (int mi = 0; mi < 4; mi++) {
            int m0 = bm + wm * 64 + mi * 16 + g;
            #pragma unroll
            for (int ni = 0; ni < 8; ni++) {
                int n = bn + wn * 64 + ni * 8 + 2 * t;
                float2 bia = *(const float2*)&bias[n];
                *(float2*)&out[(size_t)m0 * N + n] =
                    make_float2(acc[mi][ni][0] + bia.x, acc[mi][ni][1] + bia.y);
                *(float2*)&out[(size_t)(m0 + 8) * N + n] =
                    make_float2(acc[mi][ni][2] + bia.x, acc[mi][ni][3] + bia.y);
            }
        }
        return;
    }

    // OP==0: stage tile (+bias) fp32 in SMEM, then write packed fp16 Q/K/V.
    float* S = (float*)smem;
    #pragma unroll
    for (int mi = 0; mi < 4; mi++) {
        int r0 = wm * 64 + mi * 16 + g;
        #pragma unroll
        for (int ni = 0; ni < 8; ni++) {
            int c = wn * 64 + ni * 8 + 2 * t;
            float2 bia = *(const float2*)&bias[bn + c];
            *(float2*)&S[r0 * EPITCH + c] =
                make_float2(acc[mi][ni][0] + bia.x, acc[mi][ni][1] + bia.y);
            *(float2*)&S[(r0 + 8) * EPITCH + c] =
                make_float2(acc[mi][ni][2] + bia.x, acc[mi][ni][3] + bia.y);
        }
    }
    __syncthreads();

    const int which = bn >> 10;          // 0=q 1=k 2=v
    const int h0 = (bn & (Cn - 1)) >> 6;
    const int b = bm >> 11;
    const int tloc = bm & (Tn - 1);

    if (which == 0) {
        uint4* q4 = (uint4*)g_qp;
        #pragma unroll 4
        for (int i = 0; i < 16; i++) {
            int u = wid * 16 + i;
            int hh = u >> 5, fi = u & 31;
            int m16l = fi >> 2, k16 = fi & 3;
            int col = hh * 64 + k16 * 16 + 2 * t;
            int rg = (m16l * 16 + g) * EPITCH, rg8 = rg + 8 * EPITCH;
            uint4 v;
            v.x = h2pk(S[rg  + col    ] * 0.125f, S[rg  + col + 1] * 0.125f);
            v.y = h2pk(S[rg8 + col    ] * 0.125f, S[rg8 + col + 1] * 0.125f);
            v.z = h2pk(S[rg  + col + 8] * 0.125f, S[rg  + col + 9] * 0.125f);
            v.w = h2pk(S[rg8 + col + 8] * 0.125f, S[rg8 + col + 9] * 0.125f);
            int bh = b * Hn + h0 + hh;
            int m16 = (tloc >> 4) + m16l;
            q4[(size_t)bh * 16384 + (m16 * 4 + k16) * 32 + lane] = v;
        }
    } else if (which == 1) {
        uint2* k2 = (uint2*)g_kp;
        #pragma unroll 4
        for (int i = 0; i < 32; i++) {
            int u = wid * 32 + i;
            int hh = u >> 6, fi = u & 63;
            int key8l = fi >> 2, dim16 = fi & 3;
            int col = hh * 64 + dim16 * 16 + 2 * t;
            int r = (key8l * 8 + g) * EPITCH;
            uint2 v;
            v.x = h2pk(S[r + col    ], S[r + col + 1]);
            v.y = h2pk(S[r + col + 8], S[r + col + 9]);
            int bh = b * Hn + h0 + hh;
            int key8 = (tloc >> 3) + key8l;
            k2[(size_t)bh * 32768 + (key8 * 4 + dim16) * 32 + lane] = v;
        }
    } else {
        uint2* v2 = (uint2*)g_vp;
        #pragma unroll 4
        for (int i = 0; i < 32; i++) {
            int u = wid * 32 + i;
            int hh = u >> 6, fi = u & 63;
            int key16l = fi >> 3, dim8 = fi & 7;
            int col = hh * 64 + dim8 * 8 + g;
            int r = (key16l * 16 + 2 * t) * EPITCH;
            uint2 v;
            v.x = h2pk(S[r + col],               S[r + EPITCH + col]);
            v.y = h2pk(S[r + 8 * EPITCH + col],  S[r + 9 * EPITCH + col]);
            int bh = b * Hn + h0 + hh;
            int key16 = (tloc >> 4) + key16l;
            v2[(size_t)bh * 32768 + (key16 * 8 + dim8) * 32 + lane] = v;
        }
    }
}

// ---------------------------------------------------------------------------
// Flash attention, fp16 m16n8k16, double-buffered K/V via cp.async.
// Block = 4 warps = 64 q rows. One __syncthreads per tile; load(kt+1)
// overlaps compute(kt). Epilogue writes g_yp in proj A-frag layout.
// ---------------------------------------------------------------------------
#define AKOF(buf) ((buf) * 16384)          // K tile (8KB) at 0 / 16384
#define AVOF(buf) (8192 + (buf) * 16384)   // V tile (8KB) at 8192 / 24576
#define ASMEM_P 32768
#define PSP 36
#define ASMEM_SZ (32768 + 4 * 16 * PSP * 4)   // 41984

__global__ __launch_bounds__(128, 4)
void attn_pk()
{
    extern __shared__ __align__(16) char asmem[];
    const uint32_t sb = smem_u32(asmem);

    const int tid  = threadIdx.x;
    const int wid  = tid >> 5;
    const int lane = tid & 31;
    const int g = lane >> 2;
    const int t = lane & 3;

    const int bh = blockIdx.x;
    const int Qi = (int)gridDim.y - 1 - (int)blockIdx.y;   // heavy tiles first
    const int qbase = Qi * 64;

    const char* kbase = (const char*)g_kp + (size_t)bh * Tn * HDn * 2;
    const char* vbase = (const char*)g_vp + (size_t)bh * Tn * HDn * 2;
    uint32_t* Ps2 = (uint32_t*)(asmem + ASMEM_P) + wid * 16 * PSP;

    // Q fragments: 4 LDG.128 from packed layout.
    uint4 qv[4];
    {
        const uint4* qsrc = (const uint4*)g_qp + (size_t)bh * 16384;
        const int m16 = Qi * 4 + wid;
        #pragma unroll
        for (int c = 0; c < 4; c++)
            qv[c] = qsrc[(m16 * 4 + c) * 32 + lane];
    }

    float o[8][4];
    #pragma unroll
    for (int d = 0; d < 8; d++) { o[d][0]=0.f; o[d][1]=0.f; o[d][2]=0.f; o[d][3]=0.f; }
    float m0 = -1e30f, m1 = -1e30f, l0 = 0.f, l1 = 0.f;

    const int row0 = qbase + wid * 16 + g;
    const int row1 = row0 + 8;

    const int nkt = Qi + 1;

    // Prefetch tile 0 into buffer 0.
    {
        const char* ks = kbase + tid * 16;
        const char* vs = vbase + tid * 16;
        #pragma unroll
        for (int i = 0; i < 4; i++) {
            cp16(sb + AKOF(0) + tid * 16 + i * 2048, ks + (size_t)i * 2048);
            cp16(sb + AVOF(0) + tid * 16 + i * 2048, vs + (size_t)i * 2048);
        }
    }
    CP_COMMIT();

    for (int kt = 0; kt < nkt; kt++) {
        const int cur = kt & 1;
        CP_WAIT(0);
        __syncthreads();   // buf[cur] full; all warps done with buf[cur^1] reads

        // Prefetch kt+1 into the other buffer (overlaps compute below).
        if (kt + 1 < nkt) {
            const int nxt = cur ^ 1;
            const char* ks = kbase + (size_t)(kt + 1) * 8192 + tid * 16;
            const char* vs = vbase + (size_t)(kt + 1) * 8192 + tid * 16;
            #pragma unroll
            for (int i = 0; i < 4; i++) {
                cp16(sb + AKOF(nxt) + tid * 16 + i * 2048, ks + (size_t)i * 2048);
                cp16(sb + AVOF(nxt) + tid * 16 + i * 2048, vs + (size_t)i * 2048);
            }
            CP_COMMIT();
        }

        // S = Q @ K^T : 4 k16 steps x 8 key8 frags.
        const uint2* Ksf = (const uint2*)(asmem + AKOF(cur));
        float s[8][4];
        #pragma unroll
        for (int n = 0; n < 8; n++) { s[n][0]=0.f; s[n][1]=0.f; s[n][2]=0.f; s[n][3]=0.f; }
        #pragma unroll
        for (int c = 0; c < 4; c++) {
            uint32_t af[4] = { qv[c].x, qv[c].y, qv[c].z, qv[c].w };
            #pragma unroll
            for (int n = 0; n < 8; n++) {
                uint2 b = Ksf[((n * 4 + c) << 5) + lane];
                mma_f16(s[n], af, b.x, b.y);
            }
        }

        if (kt == Qi) {
            #pragma unroll
            for (int n = 0; n < 8; n++) {
                int col = kt * 64 + 8*n + 2*t;
                if (col     > row0) s[n][0] = -1e30f;
                if (col + 1 > row0) s[n][1] = -1e30f;
                if (col     > row1) s[n][2] = -1e30f;
                if (col + 1 > row1) s[n][3] = -1e30f;
            }
        }

        float mx0 = m0, mx1 = m1;
        #pragma unroll
        for (int n = 0; n < 8; n++) {
            mx0 = fmaxf(mx0, fmaxf(s[n][0], s[n][1]));
            mx1 = fmaxf(mx1, fmaxf(s[n][2], s[n][3]));
        }
        mx0 = fmaxf(mx0, __shfl_xor_sync(0xffffffff, mx0, 1));
        mx0 = fmaxf(mx0, __shfl_xor_sync(0xffffffff, mx0, 2));
        mx1 = fmaxf(mx1, __shfl_xor_sync(0xffffffff, mx1, 1));
        mx1 = fmaxf(mx1, __shfl_xor_sync(0xffffffff, mx1, 2));
        float corr0 = __expf(m0 - mx0);
        float corr1 = __expf(m1 - mx1);
        m0 = mx0; m1 = mx1;

        float rs0 = 0.f, rs1 = 0.f;
        #pragma unroll
        for (int n = 0; n < 8; n++) {
            s[n][0] = __expf(s[n][0] - m0);
            s[n][1] = __expf(s[n][1] - m0);
            s[n][2] = __expf(s[n][2] - m1);
            s[n][3] = __expf(s[n][3] - m1);
            rs0 += s[n][0] + s[n][1];
            rs1 += s[n][2] + s[n][3];
        }
        rs0 += __shfl_xor_sync(0xffffffff, rs0, 1);
        rs0 += __shfl_xor_sync(0xffffffff, rs0, 2);
        rs1 += __shfl_xor_sync(0xffffffff, rs1, 1);
        rs1 += __shfl_xor_sync(0xffffffff, rs1, 2);
        l0 = l0 * corr0 + rs0;
        l1 = l1 * corr1 + rs1;
        #pragma unroll
        for (int d = 0; d < 8; d++) {
            o[d][0] *= corr0; o[d][1] *= corr0;
            o[d][2] *= corr1; o[d][3] *= corr1;
        }

        // Stage P as half2 (per-warp region).
        #pragma unroll
        for (int n = 0; n < 8; n++) {
            Ps2[g * PSP + 4*n + t]       = h2pk(s[n][0], s[n][1]);
            Ps2[(g + 8) * PSP + 4*n + t] = h2pk(s[n][2], s[n][3]);
        }
        __syncwarp();

        // O += P @ V : 4 key16 steps x 8 dim8 frags.
        const uint2* Vsf = (const uint2*)(asmem + AVOF(cur));
        #pragma unroll
        for (int c = 0; c < 4; c++) {
            uint32_t a[4];
            a[0] = Ps2[g * PSP + c * 8 + t];
            a[1] = Ps2[(g + 8) * PSP + c * 8 + t];
            a[2] = Ps2[g * PSP + c * 8 + t + 4];
            a[3] = Ps2[(g + 8) * PSP + c * 8 + t + 4];
            #pragma unroll
            for (int d = 0; d < 8; d++) {
                uint2 b = Vsf[((c * 8 + d) << 5) + lane];
                mma_f16(o[d], a, b.x, b.y);
            }
        }
        __syncwarp();
    }

    // Epilogue: O /= l -> half2 bounce -> g_yp in proj A-frag layout.
    float inv0 = 1.f / l0, inv1 = 1.f / l1;
    #pragma unroll
    for (int d = 0; d < 8; d++) {
        Ps2[g * PSP + 4*d + t]       = h2pk(o[d][0] * inv0, o[d][1] * inv0);
        Ps2[(g + 8) * PSP + 4*d + t] = h2pk(o[d][2] * inv1, o[d][3] * inv1);
    }
    __syncwarp();

    const int b = bh / Hn, h = bh % Hn;
    const int m16 = (b * Tn + qbase + wid * 16) >> 4;
    uint4* yp4 = (uint4*)g_yp;
    #pragma unroll
    for (int k = 0; k < 4; k++) {
        uint4 v;
        v.x = Ps2[g * PSP + k * 8 + t];
        v.y = Ps2[(g + 8) * PSP + k * 8 + t];
        v.z = Ps2[g * PSP + k * 8 + t + 4];
        v.w = Ps2[(g + 8) * PSP + k * 8 + t + 4];
        yp4[(size_t)(m16 * 64 + h * 4 + k) * 32 + lane] = v;
    }
}

// ---------------------------------------------------------------------------
extern "C" void kernel_launch(void* const* d_in, const int* in_sizes, int n_in,
                              void* d_out, int out_size)
{
    const float* x      = (const float*)d_in[0];
    const float* w_attn = (const float*)d_in[1];
    const float* b_attn = (const float*)d_in[2];
    const float* w_proj = (const float*)d_in[3];
    const float* b_proj = (const float*)d_in[4];
    float* out = (float*)d_out;

    cudaFuncSetAttribute(gemm_pk<0>, cudaFuncAttributeMaxDynamicSharedMemorySize, GSMEM0_SZ);
    cudaFuncSetAttribute(gemm_pk<1>, cudaFuncAttributeMaxDynamicSharedMemorySize, GSMEM1_SZ);
    cudaFuncSetAttribute(attn_pk,    cudaFuncAttributeMaxDynamicSharedMemorySize, ASMEM_SZ);

    __half* xp; cudaGetSymbolAddress((void**)&xp, g_xp);
    __half* wt; cudaGetSymbolAddress((void**)&wt, g_wt);
    __half* wp; cudaGetSymbolAddress((void**)&wp, g_wp);

    // 0) Prep: pack x and weights into fp16 fragment layouts.
    pack_a<<<dim3(BTn / 16, Cn / 256), 256>>>(x, xp, Cn);
    pack_b<<<dim3(3 * Cn / 64, Cn / 64), 256>>>(w_attn, wt, Cn, 3 * Cn);
    pack_b<<<dim3(Cn / 64, Cn / 64), 256>>>(w_proj, wp, Cn, Cn);

    // 1) QKV GEMM -> g_qp/g_kp/g_vp (attention fragment layouts, fused pack).
    {
        dim3 grid(3 * Cn / 128, BTn / 128);   // (24, 32)
        gemm_pk<0><<<grid, 128, GSMEM0_SZ>>>(wt, b_attn, nullptr, BTn, 3 * Cn, Cn);
    }
    // 2) Causal flash attention -> g_yp (proj A-frag layout, fused pack).
    {
        dim3 grid(Bn * Hn, Tn / 64);
        attn_pk<<<grid, 128, ASMEM_SZ>>>();
    }
    // 3) Projection GEMM: g_yp @ w_proj + b_proj -> out (fp32).
    {
        dim3 grid(Cn / 128, BTn / 128);       // (8, 32)
        gemm_pk<1><<<grid, 128, GSMEM1_SZ>>>(wp, b_proj, out, BTn, Cn, Cn);
    }
}

// round 13
// speedup vs baseline: 1.0375x; 1.0375x over previous
#include <cuda_runtime.h>
#include <cuda_fp16.h>
#include <cstdint>

#define Bn 2
#define Tn 2048
#define Cn 1024
#define Hn 16
#define HDn 64
#define BTn (Bn*Tn)

// Scratch (no allocations allowed) — all fp16 in packed fragment layouts.
__device__ __half g_qp[Bn*Hn*Tn*HDn];     // Q A-frag (per head), *0.125
__device__ __half g_kp[Bn*Hn*Tn*HDn];     // K B-frag (S)
__device__ __half g_vp[Bn*Hn*Tn*HDn];     // V B-frag (PV)
__device__ __half g_xp[(size_t)BTn*Cn];   // x, A-frag
__device__ __half g_yp[(size_t)BTn*Cn];   // attn out, A-frag
__device__ __half g_wt[3*Cn*Cn];          // w_attn, B-frag
__device__ __half g_wp[Cn*Cn];            // w_proj, B-frag

__device__ __forceinline__ uint32_t h2pk(float a, float b) {
    __half2 h = __floats2half2_rn(a, b);
    return *(uint32_t*)&h;
}

__device__ __forceinline__ uint32_t smem_u32(const void* p) {
    uint32_t a;
    asm("{ .reg .u64 t; cvta.to.shared.u64 t, %1; cvt.u32.u64 %0, t; }"
        : "=r"(a) : "l"(p));
    return a;
}

__device__ __forceinline__ void cp16(uint32_t sdst, const void* gsrc) {
    asm volatile("cp.async.cg.shared.global [%0], [%1], 16;"
                 :: "r"(sdst), "l"(gsrc) : "memory");
}
#define CP_COMMIT() asm volatile("cp.async.commit_group;" ::: "memory")
#define CP_WAIT(n)  asm volatile("cp.async.wait_group %0;" :: "n"(n) : "memory")

// D = A@B + D, m16n8k16 fp16 inputs, fp32 accum. A row-major, B col-major.
__device__ __forceinline__ void mma_f16(float* d, const uint32_t* a, uint32_t b0, uint32_t b1) {
    asm volatile("mma.sync.aligned.m16n8k16.row.col.f32.f16.f16.f32 "
        "{%0,%1,%2,%3}, {%4,%5,%6,%7}, {%8,%9}, {%0,%1,%2,%3};\n"
        : "+f"(d[0]), "+f"(d[1]), "+f"(d[2]), "+f"(d[3])
        : "r"(a[0]), "r"(a[1]), "r"(a[2]), "r"(a[3]), "r"(b0), "r"(b1));
}

// ---------------------------------------------------------------------------
// Pack bodies (device): A-frag and B-frag layouts for m16n8k16.
// ---------------------------------------------------------------------------
__device__ void pack_a_body(const float* __restrict__ src, __half* __restrict__ dst,
                            int K, int m16, int k0, float* sm)
{
    float (*s)[260] = (float(*)[260])sm;
    const int K16 = K >> 4;
    const int tid = threadIdx.x;

    #pragma unroll
    for (int i = 0; i < 4; i++) {
        int j = tid + 256 * i;
        int r = j >> 6, c4 = (j & 63) * 4;
        *(float4*)&s[r][c4] = *(const float4*)(src + (size_t)(m16 * 16 + r) * K + k0 + c4);
    }
    __syncthreads();
    uint4* d4 = (uint4*)dst;
    #pragma unroll
    for (int i = 0; i < 2; i++) {
        int item = tid + 256 * i;
        int k16f = item >> 5, lane = item & 31;
        int g = lane >> 2, t = lane & 3;
        int c = k16f * 16 + 2 * t;
        uint4 v;
        v.x = h2pk(s[g    ][c],     s[g    ][c + 1]);
        v.y = h2pk(s[g + 8][c],     s[g + 8][c + 1]);
        v.z = h2pk(s[g    ][c + 8], s[g    ][c + 9]);
        v.w = h2pk(s[g + 8][c + 8], s[g + 8][c + 9]);
        d4[(size_t)(m16 * K16 + (k0 >> 4) + k16f) * 32 + lane] = v;
    }
}

__device__ void pack_b_body(const float* __restrict__ W, __half* __restrict__ dst,
                            int K, int N, int n0, int k0, float* sm)
{
    float (*s)[68] = (float(*)[68])sm;
    const int K16 = K >> 4;
    const int tid = threadIdx.x;

    #pragma unroll
    for (int i = 0; i < 4; i++) {
        int j = tid + 256 * i;
        int r = j >> 4, c4 = (j & 15) * 4;
        *(float4*)&s[r][c4] = *(const float4*)(W + (size_t)(k0 + r) * N + n0 + c4);
    }
    __syncthreads();
    uint2* d2 = (uint2*)dst;
    #pragma unroll
    for (int i = 0; i < 4; i++) {
        int item = tid + 256 * i;
        int f = item >> 5, lane = item & 31;
        int n8f = f >> 2, k16f = f & 3;
        int g = lane >> 2, t = lane & 3;
        int r = k16f * 16 + 2 * t, c = n8f * 8 + g;
        uint2 v;
        v.x = h2pk(s[r    ][c], s[r + 1][c]);
        v.y = h2pk(s[r + 8][c], s[r + 9][c]);
        d2[(size_t)(((n0 >> 3) + n8f) * K16 + (k0 >> 4) + k16f) * 32 + lane] = v;
    }
}

// Single fused pack launch: 1024 pack_a(x) + 768 pack_b(w_attn) + 256 pack_b(w_proj).
__global__ __launch_bounds__(256)
void pack_all(const float* __restrict__ x,
              const float* __restrict__ wa,
              const float* __restrict__ wpj)
{
    __shared__ float sm[64 * 68];
    const int id = blockIdx.x;
    if (id < 1024) {
        pack_a_body(x, g_xp, Cn, id & 255, (id >> 8) * 256, sm);
    } else if (id < 1792) {
        int j = id - 1024;
        pack_b_body(wa, g_wt, Cn, 3 * Cn, (j % 48) * 64, (j / 48) * 64, sm);
    } else {
        int j = id - 1792;
        pack_b_body(wpj, g_wp, Cn, Cn, (j & 15) * 64, (j >> 4) * 64, sm);
    }
}

// ---------------------------------------------------------------------------
// fp16 mma.sync GEMM on fragment-packed inputs, with explicit fragment
// double-buffering in the inner loop (LDS for kk+1 issued before mmas of kk).
// ---------------------------------------------------------------------------
#define EPITCH 132
#define GSMEM0_SZ (128 * EPITCH * 4)
#define GSMEM1_SZ (4 * 16384)

template<int OP>
__global__ __launch_bounds__(128, 2)
void gemm_pk(const __half* __restrict__ WTp,
             const float* __restrict__ bias,
             float* __restrict__ out,
             int M, int N, int K)
{
    extern __shared__ __align__(16) char smem[];
    const __half* AP = (OP == 0) ? g_xp : g_yp;
    const int K16 = K >> 4;

    const int tid  = threadIdx.x;
    const int wid  = tid >> 5;
    const int lane = tid & 31;
    const int g = lane >> 2;
    const int t = lane & 3;
    const int wm = wid >> 1;
    const int wn = wid & 1;
    const int bm = blockIdx.y * 128;
    const int bn = blockIdx.x * 128;
    const int bm16 = bm >> 4;
    const int bn8  = bn >> 3;

    const uint32_t sb = smem_u32(smem);
    const char* pa = (const char*)AP + ((size_t)bm16 * K16) * 512 + (size_t)tid * 16;
    const char* pb = (const char*)WTp + ((size_t)(bn8 + (tid >> 6)) * K16) * 256
                     + (size_t)(tid & 63) * 16;
    const uint32_t adst = sb + tid * 16;
    const uint32_t bdst = sb + 32768 + (tid >> 6) * 1024 + (tid & 63) * 16;

    float acc[4][8][4];
    #pragma unroll
    for (int mi = 0; mi < 4; mi++)
        #pragma unroll
        for (int ni = 0; ni < 8; ni++)
            #pragma unroll
            for (int e = 0; e < 4; e++) acc[mi][ni][e] = 0.f;

    const int NIT = K / 64;

    #pragma unroll
    for (int i = 0; i < 8; i++) {
        cp16(adst + i * 2048, pa + (size_t)i * K16 * 512);
        cp16(bdst + i * 2048, pb + (size_t)(2 * i) * K16 * 256);
    }
    CP_COMMIT();

    for (int it = 0; it < NIT; it++) {
        const int cur = it & 1;
        if (it + 1 < NIT) {
            const int nxt = cur ^ 1;
            const size_t ao = (size_t)(it + 1) * 2048;
            const size_t bo = (size_t)(it + 1) * 1024;
            #pragma unroll
            for (int i = 0; i < 8; i++) {
                cp16(adst + nxt * 16384 + i * 2048, pa + (size_t)i * K16 * 512 + ao);
                cp16(bdst + nxt * 16384 + i * 2048, pb + (size_t)(2 * i) * K16 * 256 + bo);
            }
            CP_COMMIT();
            CP_WAIT(1);
        } else {
            CP_WAIT(0);
        }
        __syncthreads();

        const char* As = smem + cur * 16384;
        const char* Bs = smem + 32768 + cur * 16384;

        uint4 afv[2][4];
        uint2 bfv[2][8];
        // Preload kk=0 fragments.
        #pragma unroll
        for (int mi = 0; mi < 4; mi++)
            afv[0][mi] = *(const uint4*)(As + ((((wm * 4 + mi) * 4 + 0) * 32 + lane) << 4));
        #pragma unroll
        for (int ni = 0; ni < 8; ni++)
            bfv[0][ni] = *(const uint2*)(Bs + ((((wn * 8 + ni) * 4 + 0) * 32 + lane) << 3));

        #pragma unroll
        for (int kk = 0; kk < 4; kk++) {
            const int cb = kk & 1;
            if (kk < 3) {
                const int nb = cb ^ 1;
                #pragma unroll
                for (int mi = 0; mi < 4; mi++)
                    afv[nb][mi] = *(const uint4*)(As + ((((wm * 4 + mi) * 4 + kk + 1) * 32 + lane) << 4));
                #pragma unroll
                for (int ni = 0; ni < 8; ni++)
                    bfv[nb][ni] = *(const uint2*)(Bs + ((((wn * 8 + ni) * 4 + kk + 1) * 32 + lane) << 3));
            }
            #pragma unroll
            for (int mi = 0; mi < 4; mi++) {
                uint32_t af[4] = { afv[cb][mi].x, afv[cb][mi].y, afv[cb][mi].z, afv[cb][mi].w };
                #pragma unroll
                for (int ni = 0; ni < 8; ni++)
                    mma_f16(acc[mi][ni], af, bfv[cb][ni].x, bfv[cb][ni].y);
            }
        }
        __syncthreads();
    }

    if (OP == 1) {
        #pragma unroll
        for (int mi = 0; mi < 4; mi++) {
            int m0 = bm + wm * 64 + mi * 16 + g;
            #pragma unroll
            for (int ni = 0; ni < 8; ni++) {
                int n = bn + wn * 64 + ni * 8 + 2 * t;
                float2 bia = *(const float2*)&bias[n];
                *(float2*)&out[(size_t)m0 * N + n] =
                    make_float2(acc[mi][ni][0] + bia.x, acc[mi][ni][1] + bia.y);
                *(float2*)&out[(size_t)(m0 + 8) * N + n] =
                    make_float2(acc[mi][ni][2] + bia.x, acc[mi][ni][3] + bia.y);
            }
        }
        return;
    }

    // OP==0: stage tile (+bias) fp32 in SMEM, then write packed fp16 Q/K/V.
    float* S = (float*)smem;
    #pragma unroll
    for (int mi = 0; mi < 4; mi++) {
        int r0 = wm * 64 + mi * 16 + g;
        #pragma unroll
        for (int ni = 0; ni < 8; ni++) {
            int c = wn * 64 + ni * 8 + 2 * t;
            float2 bia = *(const float2*)&bias[bn + c];
            *(float2*)&S[r0 * EPITCH + c] =
                make_float2(acc[mi][ni][0] + bia.x, acc[mi][ni][1] + bia.y);
            *(float2*)&S[(r0 + 8) * EPITCH + c] =
                make_float2(acc[mi][ni][2] + bia.x, acc[mi][ni][3] + bia.y);
        }
    }
    __syncthreads();

    const int which = bn >> 10;          // 0=q 1=k 2=v
    const int h0 = (bn & (Cn - 1)) >> 6;
    const int b = bm >> 11;
    const int tloc = bm & (Tn - 1);

    if (which == 0) {
        uint4* q4 = (uint4*)g_qp;
        #pragma unroll 4
        for (int i = 0; i < 16; i++) {
            int u = wid * 16 + i;
            int hh = u >> 5, fi = u & 31;
            int m16l = fi >> 2, k16 = fi & 3;
            int col = hh * 64 + k16 * 16 + 2 * t;
            int rg = (m16l * 16 + g) * EPITCH, rg8 = rg + 8 * EPITCH;
            uint4 v;
            v.x = h2pk(S[rg  + col    ] * 0.125f, S[rg  + col + 1] * 0.125f);
            v.y = h2pk(S[rg8 + col    ] * 0.125f, S[rg8 + col + 1] * 0.125f);
            v.z = h2pk(S[rg  + col + 8] * 0.125f, S[rg  + col + 9] * 0.125f);
            v.w = h2pk(S[rg8 + col + 8] * 0.125f, S[rg8 + col + 9] * 0.125f);
            int bh = b * Hn + h0 + hh;
            int m16 = (tloc >> 4) + m16l;
            q4[(size_t)bh * 16384 + (m16 * 4 + k16) * 32 + lane] = v;
        }
    } else if (which == 1) {
        uint2* k2 = (uint2*)g_kp;
        #pragma unroll 4
        for (int i = 0; i < 32; i++) {
            int u = wid * 32 + i;
            int hh = u >> 6, fi = u & 63;
            int key8l = fi >> 2, dim16 = fi & 3;
            int col = hh * 64 + dim16 * 16 + 2 * t;
            int r = (key8l * 8 + g) * EPITCH;
            uint2 v;
            v.x = h2pk(S[r + col    ], S[r + col + 1]);
            v.y = h2pk(S[r + col + 8], S[r + col + 9]);
            int bh = b * Hn + h0 + hh;
            int key8 = (tloc >> 3) + key8l;
            k2[(size_t)bh * 32768 + (key8 * 4 + dim16) * 32 + lane] = v;
        }
    } else {
        uint2* v2 = (uint2*)g_vp;
        #pragma unroll 4
        for (int i = 0; i < 32; i++) {
            int u = wid * 32 + i;
            int hh = u >> 6, fi = u & 63;
            int key16l = fi >> 3, dim8 = fi & 7;
            int col = hh * 64 + dim8 * 8 + g;
            int r = (key16l * 16 + 2 * t) * EPITCH;
            uint2 v;
            v.x = h2pk(S[r + col],               S[r + EPITCH + col]);
            v.y = h2pk(S[r + 8 * EPITCH + col],  S[r + 9 * EPITCH + col]);
            int bh = b * Hn + h0 + hh;
            int key16 = (tloc >> 4) + key16l;
            v2[(size_t)bh * 32768 + (key16 * 8 + dim8) * 32 + lane] = v;
        }
    }
}

// ---------------------------------------------------------------------------
// Flash attention, fp16 m16n8k16 (round-11 exact: single-buffer K/V).
// ---------------------------------------------------------------------------
#define ASMEM_K 0
#define ASMEM_V 8192
#define ASMEM_P 16384
#define PSP 36
#define ASMEM_SZ (16384 + 4 * 16 * PSP * 4)      // 25600

__global__ __launch_bounds__(128, 4)
void attn_pk()
{
    extern __shared__ __align__(16) char asmem[];
    const uint32_t sb = smem_u32(asmem);

    const int tid  = threadIdx.x;
    const int wid  = tid >> 5;
    const int lane = tid & 31;
    const int g = lane >> 2;
    const int t = lane & 3;

    const int bh = blockIdx.x;
    const int Qi = (int)gridDim.y - 1 - (int)blockIdx.y;   // heavy tiles first
    const int qbase = Qi * 64;

    const char* kbase = (const char*)g_kp + (size_t)bh * Tn * HDn * 2;
    const char* vbase = (const char*)g_vp + (size_t)bh * Tn * HDn * 2;
    uint32_t* Ps2 = (uint32_t*)(asmem + ASMEM_P) + wid * 16 * PSP;

    uint4 qv[4];
    {
        const uint4* qsrc = (const uint4*)g_qp + (size_t)bh * 16384;
        const int m16 = Qi * 4 + wid;
        #pragma unroll
        for (int c = 0; c < 4; c++)
            qv[c] = qsrc[(m16 * 4 + c) * 32 + lane];
    }

    float o[8][4];
    #pragma unroll
    for (int d = 0; d < 8; d++) { o[d][0]=0.f; o[d][1]=0.f; o[d][2]=0.f; o[d][3]=0.f; }
    float m0 = -1e30f, m1 = -1e30f, l0 = 0.f, l1 = 0.f;

    const int row0 = qbase + wid * 16 + g;
    const int row1 = row0 + 8;

    const int nkt = Qi + 1;
    for (int kt = 0; kt < nkt; kt++) {
        __syncthreads();
        {
            const char* ks = kbase + (size_t)kt * 8192 + tid * 16;
            const char* vs = vbase + (size_t)kt * 8192 + tid * 16;
            #pragma unroll
            for (int i = 0; i < 4; i++) {
                cp16(sb + ASMEM_K + tid * 16 + i * 2048, ks + (size_t)i * 2048);
                cp16(sb + ASMEM_V + tid * 16 + i * 2048, vs + (size_t)i * 2048);
            }
        }
        CP_COMMIT();
        CP_WAIT(0);
        __syncthreads();

        const uint2* Ksf = (const uint2*)(asmem + ASMEM_K);
        float s[8][4];
        #pragma unroll
        for (int n = 0; n < 8; n++) { s[n][0]=0.f; s[n][1]=0.f; s[n][2]=0.f; s[n][3]=0.f; }
        #pragma unroll
        for (int c = 0; c < 4; c++) {
            uint32_t af[4] = { qv[c].x, qv[c].y, qv[c].z, qv[c].w };
            #pragma unroll
            for (int n = 0; n < 8; n++) {
                uint2 b = Ksf[((n * 4 + c) << 5) + lane];
                mma_f16(s[n], af, b.x, b.y);
            }
        }

        if (kt == Qi) {
            #pragma unroll
            for (int n = 0; n < 8; n++) {
                int col = kt * 64 + 8*n + 2*t;
                if (col     > row0) s[n][0] = -1e30f;
                if (col + 1 > row0) s[n][1] = -1e30f;
                if (col     > row1) s[n][2] = -1e30f;
                if (col + 1 > row1) s[n][3] = -1e30f;
            }
        }

        float mx0 = m0, mx1 = m1;
        #pragma unroll
        for (int n = 0; n < 8; n++) {
            mx0 = fmaxf(mx0, fmaxf(s[n][0], s[n][1]));
            mx1 = fmaxf(mx1, fmaxf(s[n][2], s[n][3]));
        }
        mx0 = fmaxf(mx0, __shfl_xor_sync(0xffffffff, mx0, 1));
        mx0 = fmaxf(mx0, __shfl_xor_sync(0xffffffff, mx0, 2));
        mx1 = fmaxf(mx1, __shfl_xor_sync(0xffffffff, mx1, 1));
        mx1 = fmaxf(mx1, __shfl_xor_sync(0xffffffff, mx1, 2));
        float corr0 = __expf(m0 - mx0);
        float corr1 = __expf(m1 - mx1);
        m0 = mx0; m1 = mx1;

        float rs0 = 0.f, rs1 = 0.f;
        #pragma unroll
        for (int n = 0; n < 8; n++) {
            s[n][0] = __expf(s[n][0] - m0);
            s[n][1] = __expf(s[n][1] - m0);
            s[n][2] = __expf(s[n][2] - m1);
            s[n][3] = __expf(s[n][3] - m1);
            rs0 += s[n][0] + s[n][1];
            rs1 += s[n][2] + s[n][3];
        }
        rs0 += __shfl_xor_sync(0xffffffff, rs0, 1);
        rs0 += __shfl_xor_sync(0xffffffff, rs0, 2);
        rs1 += __shfl_xor_sync(0xffffffff, rs1, 1);
        rs1 += __shfl_xor_sync(0xffffffff, rs1, 2);
        l0 = l0 * corr0 + rs0;
        l1 = l1 * corr1 + rs1;
        #pragma unroll
        for (int d = 0; d < 8; d++) {
            o[d][0] *= corr0; o[d][1] *= corr0;
            o[d][2] *= corr1; o[d][3] *= corr1;
        }

        #pragma unroll
        for (int n = 0; n < 8; n++) {
            Ps2[g * PSP + 4*n + t]       = h2pk(s[n][0], s[n][1]);
            Ps2[(g + 8) * PSP + 4*n + t] = h2pk(s[n][2], s[n][3]);
        }
        __syncwarp();

        const uint2* Vsf = (const uint2*)(asmem + ASMEM_V);
        #pragma unroll
        for (int c = 0; c < 4; c++) {
            uint32_t a[4];
            a[0] = Ps2[g * PSP + c * 8 + t];
            a[1] = Ps2[(g + 8) * PSP + c * 8 + t];
            a[2] = Ps2[g * PSP + c * 8 + t + 4];
            a[3] = Ps2[(g + 8) * PSP + c * 8 + t + 4];
            #pragma unroll
            for (int d = 0; d < 8; d++) {
                uint2 b = Vsf[((c * 8 + d) << 5) + lane];
                mma_f16(o[d], a, b.x, b.y);
            }
        }
        __syncwarp();
    }

    // Epilogue: O /= l -> half2 bounce -> g_yp in proj A-frag layout.
    float inv0 = 1.f / l0, inv1 = 1.f / l1;
    #pragma unroll
    for (int d = 0; d < 8; d++) {
        Ps2[g * PSP + 4*d + t]       = h2pk(o[d][0] * inv0, o[d][1] * inv0);
        Ps2[(g + 8) * PSP + 4*d + t] = h2pk(o[d][2] * inv1, o[d][3] * inv1);
    }
    __syncwarp();

    const int b = bh / Hn, h = bh % Hn;
    const int m16 = (b * Tn + qbase + wid * 16) >> 4;
    uint4* yp4 = (uint4*)g_yp;
    #pragma unroll
    for (int k = 0; k < 4; k++) {
        uint4 v;
        v.x = Ps2[g * PSP + k * 8 + t];
        v.y = Ps2[(g + 8) * PSP + k * 8 + t];
        v.z = Ps2[g * PSP + k * 8 + t + 4];
        v.w = Ps2[(g + 8) * PSP + k * 8 + t + 4];
        yp4[(size_t)(m16 * 64 + h * 4 + k) * 32 + lane] = v;
    }
}

// ---------------------------------------------------------------------------
extern "C" void kernel_launch(void* const* d_in, const int* in_sizes, int n_in,
                              void* d_out, int out_size)
{
    const float* x      = (const float*)d_in[0];
    const float* w_attn = (const float*)d_in[1];
    const float* b_attn = (const float*)d_in[2];
    const float* w_proj = (const float*)d_in[3];
    const float* b_proj = (const float*)d_in[4];
    float* out = (float*)d_out;

    cudaFuncSetAttribute(gemm_pk<0>, cudaFuncAttributeMaxDynamicSharedMemorySize, GSMEM0_SZ);
    cudaFuncSetAttribute(gemm_pk<1>, cudaFuncAttributeMaxDynamicSharedMemorySize, GSMEM1_SZ);
    cudaFuncSetAttribute(attn_pk,    cudaFuncAttributeMaxDynamicSharedMemorySize, ASMEM_SZ);

    __half* wt; cudaGetSymbolAddress((void**)&wt, g_wt);
    __half* wp; cudaGetSymbolAddress((void**)&wp, g_wp);

    // 0) Prep: one fused pack launch (x -> A-frag, weights -> B-frag).
    pack_all<<<2048, 256>>>(x, w_attn, w_proj);

    // 1) QKV GEMM -> g_qp/g_kp/g_vp (attention fragment layouts, fused pack).
    {
        dim3 grid(3 * Cn / 128, BTn / 128);   // (24, 32)
        gemm_pk<0><<<grid, 128, GSMEM0_SZ>>>(wt, b_attn, nullptr, BTn, 3 * Cn, Cn);
    }
    // 2) Causal flash attention -> g_yp (proj A-frag layout, fused pack).
    {
        dim3 grid(Bn * Hn, Tn / 64);
        attn_pk<<<grid, 128, ASMEM_SZ>>>();
    }
    // 3) Projection GEMM: g_yp @ w_proj + b_proj -> out (fp32).
    {
        dim3 grid(Cn / 128, BTn / 128);       // (8, 32)
        gemm_pk<1><<<grid, 128, GSMEM1_SZ>>>(wp, b_proj, out, BTn, Cn, Cn);
    }
}

// round 14
// speedup vs baseline: 1.0689x; 1.0303x over previous
#include <cuda_runtime.h>
#include <cuda_fp16.h>
#include <cstdint>

#define Bn 2
#define Tn 2048
#define Cn 1024
#define Hn 16
#define HDn 64
#define BTn (Bn*Tn)

// Scratch (no allocations allowed) — all fp16 in packed fragment layouts.
__device__ __half g_qp[Bn*Hn*Tn*HDn];     // Q A-frag (per head), *0.125*log2e
__device__ __half g_kp[Bn*Hn*Tn*HDn];     // K B-frag (S)
__device__ __half g_vp[Bn*Hn*Tn*HDn];     // V B-frag (PV)
__device__ __half g_xp[(size_t)BTn*Cn];   // x, A-frag
__device__ __half g_yp[(size_t)BTn*Cn];   // attn out, A-frag
__device__ __half g_wt[3*Cn*Cn];          // w_attn, B-frag
__device__ __half g_wp[Cn*Cn];            // w_proj, B-frag

__device__ __forceinline__ uint32_t h2pk(float a, float b) {
    __half2 h = __floats2half2_rn(a, b);
    return *(uint32_t*)&h;
}
__device__ __forceinline__ uint32_t ex2h2(uint32_t x) {
    uint32_t r;
    asm("ex2.approx.f16x2 %0, %1;" : "=r"(r) : "r"(x));
    return r;
}

__device__ __forceinline__ uint32_t smem_u32(const void* p) {
    uint32_t a;
    asm("{ .reg .u64 t; cvta.to.shared.u64 t, %1; cvt.u32.u64 %0, t; }"
        : "=r"(a) : "l"(p));
    return a;
}

__device__ __forceinline__ void cp16(uint32_t sdst, const void* gsrc) {
    asm volatile("cp.async.cg.shared.global [%0], [%1], 16;"
                 :: "r"(sdst), "l"(gsrc) : "memory");
}
#define CP_COMMIT() asm volatile("cp.async.commit_group;" ::: "memory")
#define CP_WAIT(n)  asm volatile("cp.async.wait_group %0;" :: "n"(n) : "memory")

// D = A@B + D, m16n8k16 fp16 inputs, fp32 accum. A row-major, B col-major.
__device__ __forceinline__ void mma_f16(float* d, const uint32_t* a, uint32_t b0, uint32_t b1) {
    asm volatile("mma.sync.aligned.m16n8k16.row.col.f32.f16.f16.f32 "
        "{%0,%1,%2,%3}, {%4,%5,%6,%7}, {%8,%9}, {%0,%1,%2,%3};\n"
        : "+f"(d[0]), "+f"(d[1]), "+f"(d[2]), "+f"(d[3])
        : "r"(a[0]), "r"(a[1]), "r"(a[2]), "r"(a[3]), "r"(b0), "r"(b1));
}

// ---------------------------------------------------------------------------
// Pack bodies (device): A-frag and B-frag layouts for m16n8k16.
// ---------------------------------------------------------------------------
__device__ void pack_a_body(const float* __restrict__ src, __half* __restrict__ dst,
                            int K, int m16, int k0, float* sm)
{
    float (*s)[260] = (float(*)[260])sm;
    const int K16 = K >> 4;
    const int tid = threadIdx.x;

    #pragma unroll
    for (int i = 0; i < 4; i++) {
        int j = tid + 256 * i;
        int r = j >> 6, c4 = (j & 63) * 4;
        *(float4*)&s[r][c4] = *(const float4*)(src + (size_t)(m16 * 16 + r) * K + k0 + c4);
    }
    __syncthreads();
    uint4* d4 = (uint4*)dst;
    #pragma unroll
    for (int i = 0; i < 2; i++) {
        int item = tid + 256 * i;
        int k16f = item >> 5, lane = item & 31;
        int g = lane >> 2, t = lane & 3;
        int c = k16f * 16 + 2 * t;
        uint4 v;
        v.x = h2pk(s[g    ][c],     s[g    ][c + 1]);
        v.y = h2pk(s[g + 8][c],     s[g + 8][c + 1]);
        v.z = h2pk(s[g    ][c + 8], s[g    ][c + 9]);
        v.w = h2pk(s[g + 8][c + 8], s[g + 8][c + 9]);
        d4[(size_t)(m16 * K16 + (k0 >> 4) + k16f) * 32 + lane] = v;
    }
}

__device__ void pack_b_body(const float* __restrict__ W, __half* __restrict__ dst,
                            int K, int N, int n0, int k0, float* sm)
{
    float (*s)[68] = (float(*)[68])sm;
    const int K16 = K >> 4;
    const int tid = threadIdx.x;

    #pragma unroll
    for (int i = 0; i < 4; i++) {
        int j = tid + 256 * i;
        int r = j >> 4, c4 = (j & 15) * 4;
        *(float4*)&s[r][c4] = *(const float4*)(W + (size_t)(k0 + r) * N + n0 + c4);
    }
    __syncthreads();
    uint2* d2 = (uint2*)dst;
    #pragma unroll
    for (int i = 0; i < 4; i++) {
        int item = tid + 256 * i;
        int f = item >> 5, lane = item & 31;
        int n8f = f >> 2, k16f = f & 3;
        int g = lane >> 2, t = lane & 3;
        int r = k16f * 16 + 2 * t, c = n8f * 8 + g;
        uint2 v;
        v.x = h2pk(s[r    ][c], s[r + 1][c]);
        v.y = h2pk(s[r + 8][c], s[r + 9][c]);
        d2[(size_t)(((n0 >> 3) + n8f) * K16 + (k0 >> 4) + k16f) * 32 + lane] = v;
    }
}

// Single fused pack launch.
__global__ __launch_bounds__(256)
void pack_all(const float* __restrict__ x,
              const float* __restrict__ wa,
              const float* __restrict__ wpj)
{
    __shared__ float sm[64 * 68];
    const int id = blockIdx.x;
    if (id < 1024) {
        pack_a_body(x, g_xp, Cn, id & 255, (id >> 8) * 256, sm);
    } else if (id < 1792) {
        int j = id - 1024;
        pack_b_body(wa, g_wt, Cn, 3 * Cn, (j % 48) * 64, (j / 48) * 64, sm);
    } else {
        int j = id - 1792;
        pack_b_body(wpj, g_wp, Cn, Cn, (j & 15) * 64, (j >> 4) * 64, sm);
    }
}

// ---------------------------------------------------------------------------
// fp16 mma.sync GEMM with fragment double-buffering (round-13).
// ---------------------------------------------------------------------------
#define EPITCH 132
#define GSMEM0_SZ (128 * EPITCH * 4)
#define GSMEM1_SZ (4 * 16384)
#define QSCALE 0.18033688f   // 0.125 * log2(e)

template<int OP>
__global__ __launch_bounds__(128, 2)
void gemm_pk(const __half* __restrict__ WTp,
             const float* __restrict__ bias,
             float* __restrict__ out,
             int M, int N, int K)
{
    extern __shared__ __align__(16) char smem[];
    const __half* AP = (OP == 0) ? g_xp : g_yp;
    const int K16 = K >> 4;

    const int tid  = threadIdx.x;
    const int wid  = tid >> 5;
    const int lane = tid & 31;
    const int g = lane >> 2;
    const int t = lane & 3;
    const int wm = wid >> 1;
    const int wn = wid & 1;
    const int bm = blockIdx.y * 128;
    const int bn = blockIdx.x * 128;
    const int bm16 = bm >> 4;
    const int bn8  = bn >> 3;

    const uint32_t sb = smem_u32(smem);
    const char* pa = (const char*)AP + ((size_t)bm16 * K16) * 512 + (size_t)tid * 16;
    const char* pb = (const char*)WTp + ((size_t)(bn8 + (tid >> 6)) * K16) * 256
                     + (size_t)(tid & 63) * 16;
    const uint32_t adst = sb + tid * 16;
    const uint32_t bdst = sb + 32768 + (tid >> 6) * 1024 + (tid & 63) * 16;

    float acc[4][8][4];
    #pragma unroll
    for (int mi = 0; mi < 4; mi++)
        #pragma unroll
        for (int ni = 0; ni < 8; ni++)
            #pragma unroll
            for (int e = 0; e < 4; e++) acc[mi][ni][e] = 0.f;

    const int NIT = K / 64;

    #pragma unroll
    for (int i = 0; i < 8; i++) {
        cp16(adst + i * 2048, pa + (size_t)i * K16 * 512);
        cp16(bdst + i * 2048, pb + (size_t)(2 * i) * K16 * 256);
    }
    CP_COMMIT();

    for (int it = 0; it < NIT; it++) {
        const int cur = it & 1;
        if (it + 1 < NIT) {
            const int nxt = cur ^ 1;
            const size_t ao = (size_t)(it + 1) * 2048;
            const size_t bo = (size_t)(it + 1) * 1024;
            #pragma unroll
            for (int i = 0; i < 8; i++) {
                cp16(adst + nxt * 16384 + i * 2048, pa + (size_t)i * K16 * 512 + ao);
                cp16(bdst + nxt * 16384 + i * 2048, pb + (size_t)(2 * i) * K16 * 256 + bo);
            }
            CP_COMMIT();
            CP_WAIT(1);
        } else {
            CP_WAIT(0);
        }
        __syncthreads();

        const char* As = smem + cur * 16384;
        const char* Bs = smem + 32768 + cur * 16384;

        uint4 afv[2][4];
        uint2 bfv[2][8];
        #pragma unroll
        for (int mi = 0; mi < 4; mi++)
            afv[0][mi] = *(const uint4*)(As + ((((wm * 4 + mi) * 4 + 0) * 32 + lane) << 4));
        #pragma unroll
        for (int ni = 0; ni < 8; ni++)
            bfv[0][ni] = *(const uint2*)(Bs + ((((wn * 8 + ni) * 4 + 0) * 32 + lane) << 3));

        #pragma unroll
        for (int kk = 0; kk < 4; kk++) {
            const int cb = kk & 1;
            if (kk < 3) {
                const int nb = cb ^ 1;
                #pragma unroll
                for (int mi = 0; mi < 4; mi++)
                    afv[nb][mi] = *(const uint4*)(As + ((((wm * 4 + mi) * 4 + kk + 1) * 32 + lane) << 4));
                #pragma unroll
                for (int ni = 0; ni < 8; ni++)
                    bfv[nb][ni] = *(const uint2*)(Bs + ((((wn * 8 + ni) * 4 + kk + 1) * 32 + lane) << 3));
            }
            #pragma unroll
            for (int mi = 0; mi < 4; mi++) {
                uint32_t af[4] = { afv[cb][mi].x, afv[cb][mi].y, afv[cb][mi].z, afv[cb][mi].w };
                #pragma unroll
                for (int ni = 0; ni < 8; ni++)
                    mma_f16(acc[mi][ni], af, bfv[cb][ni].x, bfv[cb][ni].y);
            }
        }
        __syncthreads();
    }

    if (OP == 1) {
        #pragma unroll
        for (int mi = 0; mi < 4; mi++) {
            int m0 = bm + wm * 64 + mi * 16 + g;
            #pragma unroll
            for (int ni = 0; ni < 8; ni++) {
                int n = bn + wn * 64 + ni * 8 + 2 * t;
                float2 bia = *(const float2*)&bias[n];
                *(float2*)&out[(size_t)m0 * N + n] =
                    make_float2(acc[mi][ni][0] + bia.x, acc[mi][ni][1] + bia.y);
                *(float2*)&out[(size_t)(m0 + 8) * N + n] =
                    make_float2(acc[mi][ni][2] + bia.x, acc[mi][ni][3] + bia.y);
            }
        }
        return;
    }

    // OP==0: stage tile (+bias) fp32 in SMEM, then write packed fp16 Q/K/V.
    float* S = (float*)smem;
    #pragma unroll
    for (int mi = 0; mi < 4; mi++) {
        int r0 = wm * 64 + mi * 16 + g;
        #pragma unroll
        for (int ni = 0; ni < 8; ni++) {
            int c = wn * 64 + ni * 8 + 2 * t;
            float2 bia = *(const float2*)&bias[bn + c];
            *(float2*)&S[r0 * EPITCH + c] =
                make_float2(acc[mi][ni][0] + bia.x, acc[mi][ni][1] + bia.y);
            *(float2*)&S[(r0 + 8) * EPITCH + c] =
                make_float2(acc[mi][ni][2] + bia.x, acc[mi][ni][3] + bia.y);
        }
    }
    __syncthreads();

    const int which = bn >> 10;          // 0=q 1=k 2=v
    const int h0 = (bn & (Cn - 1)) >> 6;
    const int b = bm >> 11;
    const int tloc = bm & (Tn - 1);

    if (which == 0) {
        uint4* q4 = (uint4*)g_qp;
        #pragma unroll 4
        for (int i = 0; i < 16; i++) {
            int u = wid * 16 + i;
            int hh = u >> 5, fi = u & 31;
            int m16l = fi >> 2, k16 = fi & 3;
            int col = hh * 64 + k16 * 16 + 2 * t;
            int rg = (m16l * 16 + g) * EPITCH, rg8 = rg + 8 * EPITCH;
            uint4 v;
            v.x = h2pk(S[rg  + col    ] * QSCALE, S[rg  + col + 1] * QSCALE);
            v.y = h2pk(S[rg8 + col    ] * QSCALE, S[rg8 + col + 1] * QSCALE);
            v.z = h2pk(S[rg  + col + 8] * QSCALE, S[rg  + col + 9] * QSCALE);
            v.w = h2pk(S[rg8 + col + 8] * QSCALE, S[rg8 + col + 9] * QSCALE);
            int bh = b * Hn + h0 + hh;
            int m16 = (tloc >> 4) + m16l;
            q4[(size_t)bh * 16384 + (m16 * 4 + k16) * 32 + lane] = v;
        }
    } else if (which == 1) {
        uint2* k2 = (uint2*)g_kp;
        #pragma unroll 4
        for (int i = 0; i < 32; i++) {
            int u = wid * 32 + i;
            int hh = u >> 6, fi = u & 63;
            int key8l = fi >> 2, dim16 = fi & 3;
            int col = hh * 64 + dim16 * 16 + 2 * t;
            int r = (key8l * 8 + g) * EPITCH;
            uint2 v;
            v.x = h2pk(S[r + col    ], S[r + col + 1]);
            v.y = h2pk(S[r + col + 8], S[r + col + 9]);
            int bh = b * Hn + h0 + hh;
            int key8 = (tloc >> 3) + key8l;
            k2[(size_t)bh * 32768 + (key8 * 4 + dim16) * 32 + lane] = v;
        }
    } else {
        uint2* v2 = (uint2*)g_vp;
        #pragma unroll 4
        for (int i = 0; i < 32; i++) {
            int u = wid * 32 + i;
            int hh = u >> 6, fi = u & 63;
            int key16l = fi >> 3, dim8 = fi & 7;
            int col = hh * 64 + dim8 * 8 + g;
            int r = (key16l * 16 + 2 * t) * EPITCH;
            uint2 v;
            v.x = h2pk(S[r + col],               S[r + EPITCH + col]);
            v.y = h2pk(S[r + 8 * EPITCH + col],  S[r + 9 * EPITCH + col]);
            int bh = b * Hn + h0 + hh;
            int key16 = (tloc >> 4) + key16l;
            v2[(size_t)bh * 32768 + (key16 * 8 + dim8) * 32 + lane] = v;
        }
    }
}

// ---------------------------------------------------------------------------
// Flash attention, fp16 m16n8k16. log2-domain softmax with ex2.approx.f16x2;
// row-sum l computed on the tensor pipe via a ones-fragment mma.
// ---------------------------------------------------------------------------
#define ASMEM_K 0
#define ASMEM_V 8192
#define ASMEM_P 16384
#define PSP 36
#define ASMEM_SZ (16384 + 4 * 16 * PSP * 4)      // 25600
#define ONES2 0x3C003C00u                        // half2(1.0, 1.0)

__global__ __launch_bounds__(128, 4)
void attn_pk()
{
    extern __shared__ __align__(16) char asmem[];
    const uint32_t sb = smem_u32(asmem);

    const int tid  = threadIdx.x;
    const int wid  = tid >> 5;
    const int lane = tid & 31;
    const int g = lane >> 2;
    const int t = lane & 3;

    const int bh = blockIdx.x;
    const int Qi = (int)gridDim.y - 1 - (int)blockIdx.y;   // heavy tiles first
    const int qbase = Qi * 64;

    const char* kbase = (const char*)g_kp + (size_t)bh * Tn * HDn * 2;
    const char* vbase = (const char*)g_vp + (size_t)bh * Tn * HDn * 2;
    uint32_t* Ps2 = (uint32_t*)(asmem + ASMEM_P) + wid * 16 * PSP;

    uint4 qv[4];
    {
        const uint4* qsrc = (const uint4*)g_qp + (size_t)bh * 16384;
        const int m16 = Qi * 4 + wid;
        #pragma unroll
        for (int c = 0; c < 4; c++)
            qv[c] = qsrc[(m16 * 4 + c) * 32 + lane];
    }

    float o[8][4];
    #pragma unroll
    for (int d = 0; d < 8; d++) { o[d][0]=0.f; o[d][1]=0.f; o[d][2]=0.f; o[d][3]=0.f; }
    float la[4] = {0.f, 0.f, 0.f, 0.f};     // l accumulator (ones-mma)
    float m0 = -1e30f, m1 = -1e30f;

    const int row0 = qbase + wid * 16 + g;
    const int row1 = row0 + 8;

    const int nkt = Qi + 1;
    for (int kt = 0; kt < nkt; kt++) {
        __syncthreads();
        {
            const char* ks = kbase + (size_t)kt * 8192 + tid * 16;
            const char* vs = vbase + (size_t)kt * 8192 + tid * 16;
            #pragma unroll
            for (int i = 0; i < 4; i++) {
                cp16(sb + ASMEM_K + tid * 16 + i * 2048, ks + (size_t)i * 2048);
                cp16(sb + ASMEM_V + tid * 16 + i * 2048, vs + (size_t)i * 2048);
            }
        }
        CP_COMMIT();
        CP_WAIT(0);
        __syncthreads();

        // S(log2 domain) = Qs @ K^T.
        const uint2* Ksf = (const uint2*)(asmem + ASMEM_K);
        float s[8][4];
        #pragma unroll
        for (int n = 0; n < 8; n++) { s[n][0]=0.f; s[n][1]=0.f; s[n][2]=0.f; s[n][3]=0.f; }
        #pragma unroll
        for (int c = 0; c < 4; c++) {
            uint32_t af[4] = { qv[c].x, qv[c].y, qv[c].z, qv[c].w };
            #pragma unroll
            for (int n = 0; n < 8; n++) {
                uint2 b = Ksf[((n * 4 + c) << 5) + lane];
                mma_f16(s[n], af, b.x, b.y);
            }
        }

        if (kt == Qi) {
            #pragma unroll
            for (int n = 0; n < 8; n++) {
                int col = kt * 64 + 8*n + 2*t;
                if (col     > row0) s[n][0] = -1e30f;
                if (col + 1 > row0) s[n][1] = -1e30f;
                if (col     > row1) s[n][2] = -1e30f;
                if (col + 1 > row1) s[n][3] = -1e30f;
            }
        }

        float mx0 = m0, mx1 = m1;
        #pragma unroll
        for (int n = 0; n < 8; n++) {
            mx0 = fmaxf(mx0, fmaxf(s[n][0], s[n][1]));
            mx1 = fmaxf(mx1, fmaxf(s[n][2], s[n][3]));
        }
        mx0 = fmaxf(mx0, __shfl_xor_sync(0xffffffff, mx0, 1));
        mx0 = fmaxf(mx0, __shfl_xor_sync(0xffffffff, mx0, 2));
        mx1 = fmaxf(mx1, __shfl_xor_sync(0xffffffff, mx1, 1));
        mx1 = fmaxf(mx1, __shfl_xor_sync(0xffffffff, mx1, 2));
        float corr0 = exp2f(m0 - mx0);
        float corr1 = exp2f(m1 - mx1);
        m0 = mx0; m1 = mx1;

        // Rescale O and l.
        #pragma unroll
        for (int d = 0; d < 8; d++) {
            o[d][0] *= corr0; o[d][1] *= corr0;
            o[d][2] *= corr1; o[d][3] *= corr1;
        }
        la[0] *= corr0; la[1] *= corr0;
        la[2] *= corr1; la[3] *= corr1;

        // P = exp2(s - m) in half2 (ex2.approx.f16x2), staged per-warp.
        #pragma unroll
        for (int n = 0; n < 8; n++) {
            Ps2[g * PSP + 4*n + t]       = ex2h2(h2pk(s[n][0] - m0, s[n][1] - m0));
            Ps2[(g + 8) * PSP + 4*n + t] = ex2h2(h2pk(s[n][2] - m1, s[n][3] - m1));
        }
        __syncwarp();

        // O += P @ V ; l += P @ 1 (ones-fragment mma).
        const uint2* Vsf = (const uint2*)(asmem + ASMEM_V);
        #pragma unroll
        for (int c = 0; c < 4; c++) {
            uint32_t a[4];
            a[0] = Ps2[g * PSP + c * 8 + t];
            a[1] = Ps2[(g + 8) * PSP + c * 8 + t];
            a[2] = Ps2[g * PSP + c * 8 + t + 4];
            a[3] = Ps2[(g + 8) * PSP + c * 8 + t + 4];
            #pragma unroll
            for (int d = 0; d < 8; d++) {
                uint2 b = Vsf[((c * 8 + d) << 5) + lane];
                mma_f16(o[d], a, b.x, b.y);
            }
            mma_f16(la, a, ONES2, ONES2);
        }
        __syncwarp();
    }

    // Epilogue: O /= l -> half2 bounce -> g_yp in proj A-frag layout.
    float inv0 = 1.f / la[0], inv1 = 1.f / la[2];
    #pragma unroll
    for (int d = 0; d < 8; d++) {
        Ps2[g * PSP + 4*d + t]       = h2pk(o[d][0] * inv0, o[d][1] * inv0);
        Ps2[(g + 8) * PSP + 4*d + t] = h2pk(o[d][2] * inv1, o[d][3] * inv1);
    }
    __syncwarp();

    const int b = bh / Hn, h = bh % Hn;
    const int m16 = (b * Tn + qbase + wid * 16) >> 4;
    uint4* yp4 = (uint4*)g_yp;
    #pragma unroll
    for (int k = 0; k < 4; k++) {
        uint4 v;
        v.x = Ps2[g * PSP + k * 8 + t];
        v.y = Ps2[(g + 8) * PSP + k * 8 + t];
        v.z = Ps2[g * PSP + k * 8 + t + 4];
        v.w = Ps2[(g + 8) * PSP + k * 8 + t + 4];
        yp4[(size_t)(m16 * 64 + h * 4 + k) * 32 + lane] = v;
    }
}

// ---------------------------------------------------------------------------
extern "C" void kernel_launch(void* const* d_in, const int* in_sizes, int n_in,
                              void* d_out, int out_size)
{
    const float* x      = (const float*)d_in[0];
    const float* w_attn = (const float*)d_in[1];
    const float* b_attn = (const float*)d_in[2];
    const float* w_proj = (const float*)d_in[3];
    const float* b_proj = (const float*)d_in[4];
    float* out = (float*)d_out;

    cudaFuncSetAttribute(gemm_pk<0>, cudaFuncAttributeMaxDynamicSharedMemorySize, GSMEM0_SZ);
    cudaFuncSetAttribute(gemm_pk<1>, cudaFuncAttributeMaxDynamicSharedMemorySize, GSMEM1_SZ);
    cudaFuncSetAttribute(attn_pk,    cudaFuncAttributeMaxDynamicSharedMemorySize, ASMEM_SZ);

    __half* wt; cudaGetSymbolAddress((void**)&wt, g_wt);
    __half* wp; cudaGetSymbolAddress((void**)&wp, g_wp);

    // 0) Prep: one fused pack launch (x -> A-frag, weights -> B-frag).
    pack_all<<<2048, 256>>>(x, w_attn, w_proj);

    // 1) QKV GEMM -> g_qp/g_kp/g_vp (attention fragment layouts, fused pack).
    {
        dim3 grid(3 * Cn / 128, BTn / 128);   // (24, 32)
        gemm_pk<0><<<grid, 128, GSMEM0_SZ>>>(wt, b_attn, nullptr, BTn, 3 * Cn, Cn);
    }
    // 2) Causal flash attention -> g_yp (proj A-frag layout, fused pack).
    {
        dim3 grid(Bn * Hn, Tn / 64);
        attn_pk<<<grid, 128, ASMEM_SZ>>>();
    }
    // 3) Projection GEMM: g_yp @ w_proj + b_proj -> out (fp32).
    {
        dim3 grid(Cn / 128, BTn / 128);       // (8, 32)
        gemm_pk<1><<<grid, 128, GSMEM1_SZ>>>(wp, b_proj, out, BTn, Cn, Cn);
    }
}

// round 15
// speedup vs baseline: 1.1280x; 1.0553x over previous
#include <cuda_runtime.h>
#include <cuda_fp16.h>
#include <cstdint>

#define Bn 2
#define Tn 2048
#define Cn 1024
#define Hn 16
#define HDn 64
#define BTn (Bn*Tn)

// Scratch (no allocations allowed) — all fp16 in packed fragment layouts.
__device__ __half g_qp[Bn*Hn*Tn*HDn];     // Q A-frag (per head), *0.125*log2e
__device__ __half g_kp[Bn*Hn*Tn*HDn];     // K B-frag (S)
__device__ __half g_vp[Bn*Hn*Tn*HDn];     // V B-frag (PV)
__device__ __half g_xp[(size_t)BTn*Cn];   // x, A-frag
__device__ __half g_yp[(size_t)BTn*Cn];   // attn out, A-frag
__device__ __half g_wt[3*Cn*Cn];          // w_attn, B-frag
__device__ __half g_wp[Cn*Cn];            // w_proj, B-frag

__device__ __forceinline__ uint32_t h2pk(float a, float b) {
    __half2 h = __floats2half2_rn(a, b);
    return *(uint32_t*)&h;
}
__device__ __forceinline__ uint32_t ex2h2(uint32_t x) {
    uint32_t r;
    asm("ex2.approx.f16x2 %0, %1;" : "=r"(r) : "r"(x));
    return r;
}

__device__ __forceinline__ uint32_t smem_u32(const void* p) {
    uint32_t a;
    asm("{ .reg .u64 t; cvta.to.shared.u64 t, %1; cvt.u32.u64 %0, t; }"
        : "=r"(a) : "l"(p));
    return a;
}

__device__ __forceinline__ void cp16(uint32_t sdst, const void* gsrc) {
    asm volatile("cp.async.cg.shared.global [%0], [%1], 16;"
                 :: "r"(sdst), "l"(gsrc) : "memory");
}
#define CP_COMMIT() asm volatile("cp.async.commit_group;" ::: "memory")
#define CP_WAIT(n)  asm volatile("cp.async.wait_group %0;" :: "n"(n) : "memory")

// D = A@B + D, m16n8k16 fp16 inputs, fp32 accum. A row-major, B col-major.
__device__ __forceinline__ void mma_f16(float* d, const uint32_t* a, uint32_t b0, uint32_t b1) {
    asm volatile("mma.sync.aligned.m16n8k16.row.col.f32.f16.f16.f32 "
        "{%0,%1,%2,%3}, {%4,%5,%6,%7}, {%8,%9}, {%0,%1,%2,%3};\n"
        : "+f"(d[0]), "+f"(d[1]), "+f"(d[2]), "+f"(d[3])
        : "r"(a[0]), "r"(a[1]), "r"(a[2]), "r"(a[3]), "r"(b0), "r"(b1));
}

// ---------------------------------------------------------------------------
// Pack bodies (device): A-frag and B-frag layouts for m16n8k16.
// ---------------------------------------------------------------------------
__device__ void pack_a_body(const float* __restrict__ src, __half* __restrict__ dst,
                            int K, int m16, int k0, float* sm)
{
    float (*s)[260] = (float(*)[260])sm;
    const int K16 = K >> 4;
    const int tid = threadIdx.x;

    #pragma unroll
    for (int i = 0; i < 4; i++) {
        int j = tid + 256 * i;
        int r = j >> 6, c4 = (j & 63) * 4;
        *(float4*)&s[r][c4] = *(const float4*)(src + (size_t)(m16 * 16 + r) * K + k0 + c4);
    }
    __syncthreads();
    uint4* d4 = (uint4*)dst;
    #pragma unroll
    for (int i = 0; i < 2; i++) {
        int item = tid + 256 * i;
        int k16f = item >> 5, lane = item & 31;
        int g = lane >> 2, t = lane & 3;
        int c = k16f * 16 + 2 * t;
        uint4 v;
        v.x = h2pk(s[g    ][c],     s[g    ][c + 1]);
        v.y = h2pk(s[g + 8][c],     s[g + 8][c + 1]);
        v.z = h2pk(s[g    ][c + 8], s[g    ][c + 9]);
        v.w = h2pk(s[g + 8][c + 8], s[g + 8][c + 9]);
        d4[(size_t)(m16 * K16 + (k0 >> 4) + k16f) * 32 + lane] = v;
    }
}

__device__ void pack_b_body(const float* __restrict__ W, __half* __restrict__ dst,
                            int K, int N, int n0, int k0, float* sm)
{
    float (*s)[68] = (float(*)[68])sm;
    const int K16 = K >> 4;
    const int tid = threadIdx.x;

    #pragma unroll
    for (int i = 0; i < 4; i++) {
        int j = tid + 256 * i;
        int r = j >> 4, c4 = (j & 15) * 4;
        *(float4*)&s[r][c4] = *(const float4*)(W + (size_t)(k0 + r) * N + n0 + c4);
    }
    __syncthreads();
    uint2* d2 = (uint2*)dst;
    #pragma unroll
    for (int i = 0; i < 4; i++) {
        int item = tid + 256 * i;
        int f = item >> 5, lane = item & 31;
        int n8f = f >> 2, k16f = f & 3;
        int g = lane >> 2, t = lane & 3;
        int r = k16f * 16 + 2 * t, c = n8f * 8 + g;
        uint2 v;
        v.x = h2pk(s[r    ][c], s[r + 1][c]);
        v.y = h2pk(s[r + 8][c], s[r + 9][c]);
        d2[(size_t)(((n0 >> 3) + n8f) * K16 + (k0 >> 4) + k16f) * 32 + lane] = v;
    }
}

// Single fused pack launch.
__global__ __launch_bounds__(256)
void pack_all(const float* __restrict__ x,
              const float* __restrict__ wa,
              const float* __restrict__ wpj)
{
    __shared__ float sm[64 * 68];
    const int id = blockIdx.x;
    if (id < 1024) {
        pack_a_body(x, g_xp, Cn, id & 255, (id >> 8) * 256, sm);
    } else if (id < 1792) {
        int j = id - 1024;
        pack_b_body(wa, g_wt, Cn, 3 * Cn, (j % 48) * 64, (j / 48) * 64, sm);
    } else {
        int j = id - 1792;
        pack_b_body(wpj, g_wp, Cn, Cn, (j & 15) * 64, (j >> 4) * 64, sm);
    }
}

// ---------------------------------------------------------------------------
// fp16 mma.sync GEMM with fragment double-buffering (round-13/14).
// ---------------------------------------------------------------------------
#define EPITCH 132
#define GSMEM0_SZ (128 * EPITCH * 4)
#define GSMEM1_SZ (4 * 16384)
#define QSCALE 0.18033688f   // 0.125 * log2(e)

template<int OP>
__global__ __launch_bounds__(128, 2)
void gemm_pk(const __half* __restrict__ WTp,
             const float* __restrict__ bias,
             float* __restrict__ out,
             int M, int N, int K)
{
    extern __shared__ __align__(16) char smem[];
    const __half* AP = (OP == 0) ? g_xp : g_yp;
    const int K16 = K >> 4;

    const int tid  = threadIdx.x;
    const int wid  = tid >> 5;
    const int lane = tid & 31;
    const int g = lane >> 2;
    const int t = lane & 3;
    const int wm = wid >> 1;
    const int wn = wid & 1;
    const int bm = blockIdx.y * 128;
    const int bn = blockIdx.x * 128;
    const int bm16 = bm >> 4;
    const int bn8  = bn >> 3;

    const uint32_t sb = smem_u32(smem);
    const char* pa = (const char*)AP + ((size_t)bm16 * K16) * 512 + (size_t)tid * 16;
    const char* pb = (const char*)WTp + ((size_t)(bn8 + (tid >> 6)) * K16) * 256
                     + (size_t)(tid & 63) * 16;
    const uint32_t adst = sb + tid * 16;
    const uint32_t bdst = sb + 32768 + (tid >> 6) * 1024 + (tid & 63) * 16;

    float acc[4][8][4];
    #pragma unroll
    for (int mi = 0; mi < 4; mi++)
        #pragma unroll
        for (int ni = 0; ni < 8; ni++)
            #pragma unroll
            for (int e = 0; e < 4; e++) acc[mi][ni][e] = 0.f;

    const int NIT = K / 64;

    #pragma unroll
    for (int i = 0; i < 8; i++) {
        cp16(adst + i * 2048, pa + (size_t)i * K16 * 512);
        cp16(bdst + i * 2048, pb + (size_t)(2 * i) * K16 * 256);
    }
    CP_COMMIT();

    for (int it = 0; it < NIT; it++) {
        const int cur = it & 1;
        if (it + 1 < NIT) {
            const int nxt = cur ^ 1;
            const size_t ao = (size_t)(it + 1) * 2048;
            const size_t bo = (size_t)(it + 1) * 1024;
            #pragma unroll
            for (int i = 0; i < 8; i++) {
                cp16(adst + nxt * 16384 + i * 2048, pa + (size_t)i * K16 * 512 + ao);
                cp16(bdst + nxt * 16384 + i * 2048, pb + (size_t)(2 * i) * K16 * 256 + bo);
            }
            CP_COMMIT();
            CP_WAIT(1);
        } else {
            CP_WAIT(0);
        }
        __syncthreads();

        const char* As = smem + cur * 16384;
        const char* Bs = smem + 32768 + cur * 16384;

        uint4 afv[2][4];
        uint2 bfv[2][8];
        #pragma unroll
        for (int mi = 0; mi < 4; mi++)
            afv[0][mi] = *(const uint4*)(As + ((((wm * 4 + mi) * 4 + 0) * 32 + lane) << 4));
        #pragma unroll
        for (int ni = 0; ni < 8; ni++)
            bfv[0][ni] = *(const uint2*)(Bs + ((((wn * 8 + ni) * 4 + 0) * 32 + lane) << 3));

        #pragma unroll
        for (int kk = 0; kk < 4; kk++) {
            const int cb = kk & 1;
            if (kk < 3) {
                const int nb = cb ^ 1;
                #pragma unroll
                for (int mi = 0; mi < 4; mi++)
                    afv[nb][mi] = *(const uint4*)(As + ((((wm * 4 + mi) * 4 + kk + 1) * 32 + lane) << 4));
                #pragma unroll
                for (int ni = 0; ni < 8; ni++)
                    bfv[nb][ni] = *(const uint2*)(Bs + ((((wn * 8 + ni) * 4 + kk + 1) * 32 + lane) << 3));
            }
            #pragma unroll
            for (int mi = 0; mi < 4; mi++) {
                uint32_t af[4] = { afv[cb][mi].x, afv[cb][mi].y, afv[cb][mi].z, afv[cb][mi].w };
                #pragma unroll
                for (int ni = 0; ni < 8; ni++)
                    mma_f16(acc[mi][ni], af, bfv[cb][ni].x, bfv[cb][ni].y);
            }
        }
        __syncthreads();
    }

    if (OP == 1) {
        #pragma unroll
        for (int mi = 0; mi < 4; mi++) {
            int m0 = bm + wm * 64 + mi * 16 + g;
            #pragma unroll
            for (int ni = 0; ni < 8; ni++) {
                int n = bn + wn * 64 + ni * 8 + 2 * t;
                float2 bia = *(const float2*)&bias[n];
                *(float2*)&out[(size_t)m0 * N + n] =
                    make_float2(acc[mi][ni][0] + bia.x, acc[mi][ni][1] + bia.y);
                *(float2*)&out[(size_t)(m0 + 8) * N + n] =
                    make_float2(acc[mi][ni][2] + bia.x, acc[mi][ni][3] + bia.y);
            }
        }
        return;
    }

    // OP==0: stage tile (+bias) fp32 in SMEM, then write packed fp16 Q/K/V.
    float* S = (float*)smem;
    #pragma unroll
    for (int mi = 0; mi < 4; mi++) {
        int r0 = wm * 64 + mi * 16 + g;
        #pragma unroll
        for (int ni = 0; ni < 8; ni++) {
            int c = wn * 64 + ni * 8 + 2 * t;
            float2 bia = *(const float2*)&bias[bn + c];
            *(float2*)&S[r0 * EPITCH + c] =
                make_float2(acc[mi][ni][0] + bia.x, acc[mi][ni][1] + bia.y);
            *(float2*)&S[(r0 + 8) * EPITCH + c] =
                make_float2(acc[mi][ni][2] + bia.x, acc[mi][ni][3] + bia.y);
        }
    }
    __syncthreads();

    const int which = bn >> 10;          // 0=q 1=k 2=v
    const int h0 = (bn & (Cn - 1)) >> 6;
    const int b = bm >> 11;
    const int tloc = bm & (Tn - 1);

    if (which == 0) {
        uint4* q4 = (uint4*)g_qp;
        #pragma unroll 4
        for (int i = 0; i < 16; i++) {
            int u = wid * 16 + i;
            int hh = u >> 5, fi = u & 31;
            int m16l = fi >> 2, k16 = fi & 3;
            int col = hh * 64 + k16 * 16 + 2 * t;
            int rg = (m16l * 16 + g) * EPITCH, rg8 = rg + 8 * EPITCH;
            uint4 v;
            v.x = h2pk(S[rg  + col    ] * QSCALE, S[rg  + col + 1] * QSCALE);
            v.y = h2pk(S[rg8 + col    ] * QSCALE, S[rg8 + col + 1] * QSCALE);
            v.z = h2pk(S[rg  + col + 8] * QSCALE, S[rg  + col + 9] * QSCALE);
            v.w = h2pk(S[rg8 + col + 8] * QSCALE, S[rg8 + col + 9] * QSCALE);
            int bh = b * Hn + h0 + hh;
            int m16 = (tloc >> 4) + m16l;
            q4[(size_t)bh * 16384 + (m16 * 4 + k16) * 32 + lane] = v;
        }
    } else if (which == 1) {
        uint2* k2 = (uint2*)g_kp;
        #pragma unroll 4
        for (int i = 0; i < 32; i++) {
            int u = wid * 32 + i;
            int hh = u >> 6, fi = u & 63;
            int key8l = fi >> 2, dim16 = fi & 3;
            int col = hh * 64 + dim16 * 16 + 2 * t;
            int r = (key8l * 8 + g) * EPITCH;
            uint2 v;
            v.x = h2pk(S[r + col    ], S[r + col + 1]);
            v.y = h2pk(S[r + col + 8], S[r + col + 9]);
            int bh = b * Hn + h0 + hh;
            int key8 = (tloc >> 3) + key8l;
            k2[(size_t)bh * 32768 + (key8 * 4 + dim16) * 32 + lane] = v;
        }
    } else {
        uint2* v2 = (uint2*)g_vp;
        #pragma unroll 4
        for (int i = 0; i < 32; i++) {
            int u = wid * 32 + i;
            int hh = u >> 6, fi = u & 63;
            int key16l = fi >> 3, dim8 = fi & 7;
            int col = hh * 64 + dim8 * 8 + g;
            int r = (key16l * 16 + 2 * t) * EPITCH;
            uint2 v;
            v.x = h2pk(S[r + col],               S[r + EPITCH + col]);
            v.y = h2pk(S[r + 8 * EPITCH + col],  S[r + 9 * EPITCH + col]);
            int bh = b * Hn + h0 + hh;
            int key16 = (tloc >> 4) + key16l;
            v2[(size_t)bh * 32768 + (key16 * 8 + dim8) * 32 + lane] = v;
        }
    }
}

// ---------------------------------------------------------------------------
// Flash attention, fp16 m16n8k16. log2-domain softmax (ex2.approx.f16x2);
// P forwarded register-to-register from S C-frags to PV A-frags (layout
// identity: C-frag(m16n8) pair == A-frag(m16k16)). No P SMEM, no bounce.
// ---------------------------------------------------------------------------
#define ASMEM_K 0
#define ASMEM_V 8192
#define ASMEM_SZ 16384
#define ONES2 0x3C003C00u                        // half2(1.0, 1.0)

__global__ __launch_bounds__(128, 4)
void attn_pk()
{
    extern __shared__ __align__(16) char asmem[];
    const uint32_t sb = smem_u32(asmem);

    const int tid  = threadIdx.x;
    const int wid  = tid >> 5;
    const int lane = tid & 31;
    const int g = lane >> 2;
    const int t = lane & 3;

    const int bh = blockIdx.x;
    const int Qi = (int)gridDim.y - 1 - (int)blockIdx.y;   // heavy tiles first
    const int qbase = Qi * 64;

    const char* kbase = (const char*)g_kp + (size_t)bh * Tn * HDn * 2;
    const char* vbase = (const char*)g_vp + (size_t)bh * Tn * HDn * 2;

    uint4 qv[4];
    {
        const uint4* qsrc = (const uint4*)g_qp + (size_t)bh * 16384;
        const int m16 = Qi * 4 + wid;
        #pragma unroll
        for (int c = 0; c < 4; c++)
            qv[c] = qsrc[(m16 * 4 + c) * 32 + lane];
    }

    float o[8][4];
    #pragma unroll
    for (int d = 0; d < 8; d++) { o[d][0]=0.f; o[d][1]=0.f; o[d][2]=0.f; o[d][3]=0.f; }
    float la[4] = {0.f, 0.f, 0.f, 0.f};     // l accumulator (ones-mma)
    float m0 = -1e30f, m1 = -1e30f;

    const int row0 = qbase + wid * 16 + g;
    const int row1 = row0 + 8;

    const int nkt = Qi + 1;
    for (int kt = 0; kt < nkt; kt++) {
        __syncthreads();
        {
            const char* ks = kbase + (size_t)kt * 8192 + tid * 16;
            const char* vs = vbase + (size_t)kt * 8192 + tid * 16;
            #pragma unroll
            for (int i = 0; i < 4; i++) {
                cp16(sb + ASMEM_K + tid * 16 + i * 2048, ks + (size_t)i * 2048);
                cp16(sb + ASMEM_V + tid * 16 + i * 2048, vs + (size_t)i * 2048);
            }
        }
        CP_COMMIT();
        CP_WAIT(0);
        __syncthreads();

        // S(log2 domain) = Qs @ K^T.
        const uint2* Ksf = (const uint2*)(asmem + ASMEM_K);
        float s[8][4];
        #pragma unroll
        for (int n = 0; n < 8; n++) { s[n][0]=0.f; s[n][1]=0.f; s[n][2]=0.f; s[n][3]=0.f; }
        #pragma unroll
        for (int c = 0; c < 4; c++) {
            uint32_t af[4] = { qv[c].x, qv[c].y, qv[c].z, qv[c].w };
            #pragma unroll
            for (int n = 0; n < 8; n++) {
                uint2 b = Ksf[((n * 4 + c) << 5) + lane];
                mma_f16(s[n], af, b.x, b.y);
            }
        }

        if (kt == Qi) {
            #pragma unroll
            for (int n = 0; n < 8; n++) {
                int col = kt * 64 + 8*n + 2*t;
                if (col     > row0) s[n][0] = -1e30f;
                if (col + 1 > row0) s[n][1] = -1e30f;
                if (col     > row1) s[n][2] = -1e30f;
                if (col + 1 > row1) s[n][3] = -1e30f;
            }
        }

        float mx0 = m0, mx1 = m1;
        #pragma unroll
        for (int n = 0; n < 8; n++) {
            mx0 = fmaxf(mx0, fmaxf(s[n][0], s[n][1]));
            mx1 = fmaxf(mx1, fmaxf(s[n][2], s[n][3]));
        }
        mx0 = fmaxf(mx0, __shfl_xor_sync(0xffffffff, mx0, 1));
        mx0 = fmaxf(mx0, __shfl_xor_sync(0xffffffff, mx0, 2));
        mx1 = fmaxf(mx1, __shfl_xor_sync(0xffffffff, mx1, 1));
        mx1 = fmaxf(mx1, __shfl_xor_sync(0xffffffff, mx1, 2));
        float corr0 = exp2f(m0 - mx0);
        float corr1 = exp2f(m1 - mx1);
        m0 = mx0; m1 = mx1;

        // Rescale O and l.
        #pragma unroll
        for (int d = 0; d < 8; d++) {
            o[d][0] *= corr0; o[d][1] *= corr0;
            o[d][2] *= corr1; o[d][3] *= corr1;
        }
        la[0] *= corr0; la[1] *= corr0;
        la[2] *= corr1; la[3] *= corr1;

        // P = exp2(s - m) in half2, kept in registers.
        // pe[n] = (row g, keys 8n+2t,+1); po[n] = (row g+8, same keys).
        uint32_t pe[8], po[8];
        #pragma unroll
        for (int n = 0; n < 8; n++) {
            pe[n] = ex2h2(h2pk(s[n][0] - m0, s[n][1] - m0));
            po[n] = ex2h2(h2pk(s[n][2] - m1, s[n][3] - m1));
        }

        // O += P @ V ; l += P @ 1. A-frag for key chunk c (16 keys) is the
        // C-frag pair (2c, 2c+1) — direct register forwarding.
        const uint2* Vsf = (const uint2*)(asmem + ASMEM_V);
        #pragma unroll
        for (int c = 0; c < 4; c++) {
            uint32_t a[4] = { pe[2*c], po[2*c], pe[2*c + 1], po[2*c + 1] };
            #pragma unroll
            for (int d = 0; d < 8; d++) {
                uint2 b = Vsf[((c * 8 + d) << 5) + lane];
                mma_f16(o[d], a, b.x, b.y);
            }
            mma_f16(la, a, ONES2, ONES2);
        }
    }

    // Epilogue: O /= l, write g_yp A-frags directly from registers
    // (same C-frag->A-frag identity: v = {o[2k] rows g/g+8, o[2k+1] rows g/g+8}).
    float inv0 = 1.f / la[0], inv1 = 1.f / la[2];
    const int b = bh / Hn, h = bh % Hn;
    const int m16 = (b * Tn + qbase + wid * 16) >> 4;
    uint4* yp4 = (uint4*)g_yp;
    #pragma unroll
    for (int k = 0; k < 4; k++) {
        uint4 v;
        v.x = h2pk(o[2*k    ][0] * inv0, o[2*k    ][1] * inv0);
        v.y = h2pk(o[2*k    ][2] * inv1, o[2*k    ][3] * inv1);
        v.z = h2pk(o[2*k + 1][0] * inv0, o[2*k + 1][1] * inv0);
        v.w = h2pk(o[2*k + 1][2] * inv1, o[2*k + 1][3] * inv1);
        yp4[(size_t)(m16 * 64 + h * 4 + k) * 32 + lane] = v;
    }
}

// ---------------------------------------------------------------------------
extern "C" void kernel_launch(void* const* d_in, const int* in_sizes, int n_in,
                              void* d_out, int out_size)
{
    const float* x      = (const float*)d_in[0];
    const float* w_attn = (const float*)d_in[1];
    const float* b_attn = (const float*)d_in[2];
    const float* w_proj = (const float*)d_in[3];
    const float* b_proj = (const float*)d_in[4];
    float* out = (float*)d_out;

    cudaFuncSetAttribute(gemm_pk<0>, cudaFuncAttributeMaxDynamicSharedMemorySize, GSMEM0_SZ);
    cudaFuncSetAttribute(gemm_pk<1>, cudaFuncAttributeMaxDynamicSharedMemorySize, GSMEM1_SZ);
    cudaFuncSetAttribute(attn_pk,    cudaFuncAttributeMaxDynamicSharedMemorySize, ASMEM_SZ);

    __half* wt; cudaGetSymbolAddress((void**)&wt, g_wt);
    __half* wp; cudaGetSymbolAddress((void**)&wp, g_wp);

    // 0) Prep: one fused pack launch (x -> A-frag, weights -> B-frag).
    pack_all<<<2048, 256>>>(x, w_attn, w_proj);

    // 1) QKV GEMM -> g_qp/g_kp/g_vp (attention fragment layouts, fused pack).
    {
        dim3 grid(3 * Cn / 128, BTn / 128);   // (24, 32)
        gemm_pk<0><<<grid, 128, GSMEM0_SZ>>>(wt, b_attn, nullptr, BTn, 3 * Cn, Cn);
    }
    // 2) Causal flash attention -> g_yp (proj A-frag layout, register epilogue).
    {
        dim3 grid(Bn * Hn, Tn / 64);
        attn_pk<<<grid, 128, ASMEM_SZ>>>();
    }
    // 3) Projection GEMM: g_yp @ w_proj + b_proj -> out (fp32).
    {
        dim3 grid(Cn / 128, BTn / 128);       // (8, 32)
        gemm_pk<1><<<grid, 128, GSMEM1_SZ>>>(wp, b_proj, out, BTn, Cn, Cn);
    }
}